// round 9
// baseline (speedup 1.0000x reference)
#include <cuda_runtime.h>
#include <cstdint>
#include <math.h>

#define N_LEVELS 16
#define LOG2_T 19
#define TABLE_SIZE (1u << LOG2_T)
#define TABLE_MASK (TABLE_SIZE - 1u)

#define THREADS 256

struct ResParams { float resm1[N_LEVELS]; };

// 8 lanes per point: lane-group k handles levels 2k and 2k+1 and writes one
// float4 of the output row (warp stores = 512B contiguous, 4 wf = floor).
// x coords fetched by ONE predicated LDG per warp (lanes c<3 load x[3p+c])
// and broadcast via __shfl_sync within each 8-lane group: cuts x-load
// wavefronts ~3x. Gathers via __ldg (R6 best); stores via __stcs (R8 win).
__global__ void __launch_bounds__(THREADS) hashgrid_kernel(
    const float* __restrict__ x,
    const float2* __restrict__ tables,
    float4* __restrict__ out,
    int n, ResParams rp)
{
    const int tid  = blockIdx.x * THREADS + threadIdx.x;
    const int p    = tid >> 3;        // point index
    const int k    = tid & 7;         // float4 slot within the output row
    const int lane = threadIdx.x & 31;

    // Warp covers points [pw, pw+4). Fast path if all 4 points valid.
    const int pw = (tid & ~31) >> 3;

    float px, py, pz;
    if (pw + 4 <= n) {
        // One load instruction per warp: lane = g*8 + c; lanes c<3 load
        // coordinate c of point pw+g. 12 active lanes span 48 bytes.
        float v = 0.0f;
        const int g = lane >> 3;
        const int c = lane & 7;
        if (c < 3) v = __ldg(&x[3 * (pw + g) + c]);
        // Broadcast within the 8-lane group (source lanes g*8 + {0,1,2}).
        const int base = lane & ~7;
        px = __shfl_sync(0xFFFFFFFFu, v, base + 0);
        py = __shfl_sync(0xFFFFFFFFu, v, base + 1);
        pz = __shfl_sync(0xFFFFFFFFu, v, base + 2);
    } else {
        if (p >= n) return;
        px = __ldg(&x[3 * p + 0]);
        py = __ldg(&x[3 * p + 1]);
        pz = __ldg(&x[3 * p + 2]);
    }
    if (p >= n) return;

    // Match reference: x_norm = (x + 1) / 2 in f32 (no FMA contraction)
    const float xn = __fmul_rn(__fadd_rn(px, 1.0f), 0.5f);
    const float yn = __fmul_rn(__fadd_rn(py, 1.0f), 0.5f);
    const float zn = __fmul_rn(__fadd_rn(pz, 1.0f), 0.5f);

    const int l0 = 2 * k;
    const int l1 = 2 * k + 1;

    const float r0 = rp.resm1[l0];
    const float r1 = rp.resm1[l1];

    // scaled = x_norm * (res - 1); truncating cast == floor (operands >= 0)
    const uint32_t gx0 = (uint32_t)__fmul_rn(xn, r0);
    const uint32_t gy0 = (uint32_t)__fmul_rn(yn, r0);
    const uint32_t gz0 = (uint32_t)__fmul_rn(zn, r0);
    const uint32_t gx1 = (uint32_t)__fmul_rn(xn, r1);
    const uint32_t gy1 = (uint32_t)__fmul_rn(yn, r1);
    const uint32_t gz1 = (uint32_t)__fmul_rn(zn, r1);

    const uint32_t h0 =
        (gx0 ^ (gy0 * 2654435761u) ^ (gz0 * 805459861u)) & TABLE_MASK;
    const uint32_t h1 =
        (gx1 ^ (gy1 * 2654435761u) ^ (gz1 * 805459861u)) & TABLE_MASK;

    const float2 f0 = __ldg(&tables[(size_t)l0 * TABLE_SIZE + h0]);
    const float2 f1 = __ldg(&tables[(size_t)l1 * TABLE_SIZE + h1]);

    // Evict-first store: output is write-once, never re-read.
    __stcs(&out[(size_t)tid], make_float4(f0.x, f0.y, f1.x, f1.y));
}

extern "C" void kernel_launch(void* const* d_in, const int* in_sizes, int n_in,
                              void* d_out, int out_size)
{
    const float*  x      = (const float*)d_in[0];
    const float2* tables = (const float2*)d_in[1];
    float4*       out    = (float4*)d_out;

    const int n = in_sizes[0] / 3;  // x has N*3 elements

    // Resolutions via the same double-precision libm chain as the Python
    // reference: b = exp((log(2048) - log(16)) / 15); res_l = int(16 * b**l).
    // Proven bit-identical (rel_err == 0.0) in prior rounds.
    ResParams rp;
    {
        const double b = exp((log(2048.0) - log(16.0)) / 15.0);
        for (int l = 0; l < N_LEVELS; l++) {
            int res = (int)(16.0 * pow(b, (double)l));
            rp.resm1[l] = (float)res - 1.0f;
        }
    }

    const long long total = (long long)n * 8;            // one thread per float4
    const int blocks = (int)((total + THREADS - 1) / THREADS);
    hashgrid_kernel<<<blocks, THREADS>>>(x, tables, out, n, rp);
}

// round 10
// speedup vs baseline: 1.0779x; 1.0779x over previous
#include <cuda_runtime.h>
#include <cstdint>
#include <math.h>

#define N_LEVELS 16
#define LOG2_T 19
#define TABLE_SIZE (1u << LOG2_T)
#define TABLE_MASK (TABLE_SIZE - 1u)

#define THREADS 256

struct ResParams { float resm1[N_LEVELS]; };

// R8 structure (8 lanes/point, coalesced 512B warp stores, __ldg gathers,
// __stcs streaming stores) + 2 output elements per thread (i and i+half)
// to double per-thread gather MLP (2 -> 4) and close the L1tex idle gap.
__global__ void __launch_bounds__(THREADS, 8) hashgrid_kernel(
    const float* __restrict__ x,
    const float2* __restrict__ tables,
    float4* __restrict__ out,
    int n, long long total, long long half, ResParams rp)
{
    const long long i0 = (long long)blockIdx.x * THREADS + threadIdx.x;
    if (i0 >= half) return;
    const long long i1 = i0 + half;
    const bool has2 = (i1 < total);

    // ---- element A ----
    const int pA = (int)(i0 >> 3);
    const int kA = (int)(i0 & 7);
    const float pxA = __ldg(&x[3 * pA + 0]);
    const float pyA = __ldg(&x[3 * pA + 1]);
    const float pzA = __ldg(&x[3 * pA + 2]);

    // ---- element B ----
    const int pB = has2 ? (int)(i1 >> 3) : pA;
    const int kB = has2 ? (int)(i1 & 7) : kA;
    const float pxB = __ldg(&x[3 * pB + 0]);
    const float pyB = __ldg(&x[3 * pB + 1]);
    const float pzB = __ldg(&x[3 * pB + 2]);

    // Match reference: x_norm = (x + 1) / 2 in f32 (no FMA contraction)
    const float xnA = __fmul_rn(__fadd_rn(pxA, 1.0f), 0.5f);
    const float ynA = __fmul_rn(__fadd_rn(pyA, 1.0f), 0.5f);
    const float znA = __fmul_rn(__fadd_rn(pzA, 1.0f), 0.5f);
    const float xnB = __fmul_rn(__fadd_rn(pxB, 1.0f), 0.5f);
    const float ynB = __fmul_rn(__fadd_rn(pyB, 1.0f), 0.5f);
    const float znB = __fmul_rn(__fadd_rn(pzB, 1.0f), 0.5f);

    const int lA0 = 2 * kA, lA1 = 2 * kA + 1;
    const int lB0 = 2 * kB, lB1 = 2 * kB + 1;
    const float rA0 = rp.resm1[lA0], rA1 = rp.resm1[lA1];
    const float rB0 = rp.resm1[lB0], rB1 = rp.resm1[lB1];

    // scaled = x_norm * (res - 1); truncating cast == floor (operands >= 0)
    const uint32_t hA0 =
        (((uint32_t)__fmul_rn(xnA, rA0)) ^
         (((uint32_t)__fmul_rn(ynA, rA0)) * 2654435761u) ^
         (((uint32_t)__fmul_rn(znA, rA0)) * 805459861u)) & TABLE_MASK;
    const uint32_t hA1 =
        (((uint32_t)__fmul_rn(xnA, rA1)) ^
         (((uint32_t)__fmul_rn(ynA, rA1)) * 2654435761u) ^
         (((uint32_t)__fmul_rn(znA, rA1)) * 805459861u)) & TABLE_MASK;
    const uint32_t hB0 =
        (((uint32_t)__fmul_rn(xnB, rB0)) ^
         (((uint32_t)__fmul_rn(ynB, rB0)) * 2654435761u) ^
         (((uint32_t)__fmul_rn(znB, rB0)) * 805459861u)) & TABLE_MASK;
    const uint32_t hB1 =
        (((uint32_t)__fmul_rn(xnB, rB1)) ^
         (((uint32_t)__fmul_rn(ynB, rB1)) * 2654435761u) ^
         (((uint32_t)__fmul_rn(znB, rB1)) * 805459861u)) & TABLE_MASK;

    // 4 independent gathers in flight (MLP=4).
    const float2 fA0 = __ldg(&tables[(size_t)lA0 * TABLE_SIZE + hA0]);
    const float2 fA1 = __ldg(&tables[(size_t)lA1 * TABLE_SIZE + hA1]);
    const float2 fB0 = __ldg(&tables[(size_t)lB0 * TABLE_SIZE + hB0]);
    const float2 fB1 = __ldg(&tables[(size_t)lB1 * TABLE_SIZE + hB1]);

    __stcs(&out[(size_t)i0], make_float4(fA0.x, fA0.y, fA1.x, fA1.y));
    if (has2)
        __stcs(&out[(size_t)i1], make_float4(fB0.x, fB0.y, fB1.x, fB1.y));
}

extern "C" void kernel_launch(void* const* d_in, const int* in_sizes, int n_in,
                              void* d_out, int out_size)
{
    const float*  x      = (const float*)d_in[0];
    const float2* tables = (const float2*)d_in[1];
    float4*       out    = (float4*)d_out;

    const int n = in_sizes[0] / 3;  // x has N*3 elements

    // Resolutions via the same double-precision libm chain as the Python
    // reference: b = exp((log(2048) - log(16)) / 15); res_l = int(16 * b**l).
    // Proven bit-identical (rel_err == 0.0) across all passing rounds.
    ResParams rp;
    {
        const double b = exp((log(2048.0) - log(16.0)) / 15.0);
        for (int l = 0; l < N_LEVELS; l++) {
            int res = (int)(16.0 * pow(b, (double)l));
            rp.resm1[l] = (float)res - 1.0f;
        }
    }

    const long long total = (long long)n * 8;     // output float4 count
    const long long half  = (total + 1) / 2;      // elements per thread-pass
    const int blocks = (int)((half + THREADS - 1) / THREADS);
    hashgrid_kernel<<<blocks, THREADS>>>(x, tables, out, n, total, half, rp);
}

// round 11
// speedup vs baseline: 1.1161x; 1.0355x over previous
#include <cuda_runtime.h>
#include <cstdint>
#include <math.h>

#define N_LEVELS 16
#define LOG2_T 19
#define TABLE_SIZE (1u << LOG2_T)
#define TABLE_MASK (TABLE_SIZE - 1u)

#define THREADS 256

struct ResParams { float resm1[N_LEVELS]; };

// R8 structure (best: 159.7us): 8 lanes per point, lane k handles levels
// 2k/2k+1, warp stores 512B contiguous (4 wf = floor), __stcs streaming
// stores. New in this round: mixed gather cache policy — levels 0-1 (lane
// k==0; hot sets 32KB+85KB) keep L1 allocation (__ldg), levels >=2 bypass
// L1 (__ldcg) so their miss streams stop thrashing the coarse working set.
__global__ void __launch_bounds__(THREADS) hashgrid_kernel(
    const float* __restrict__ x,
    const float2* __restrict__ tables,
    float4* __restrict__ out,
    int n, ResParams rp)
{
    const int tid = blockIdx.x * THREADS + threadIdx.x;
    const int p   = tid >> 3;       // point index
    const int k   = tid & 7;        // float4 slot within the output row
    if (p >= n) return;

    // 8 lanes share these addresses -> L1 broadcast, ~free.
    const float px = __ldg(&x[3 * p + 0]);
    const float py = __ldg(&x[3 * p + 1]);
    const float pz = __ldg(&x[3 * p + 2]);

    // Match reference: x_norm = (x + 1) / 2 in f32 (no FMA contraction)
    const float xn = __fmul_rn(__fadd_rn(px, 1.0f), 0.5f);
    const float yn = __fmul_rn(__fadd_rn(py, 1.0f), 0.5f);
    const float zn = __fmul_rn(__fadd_rn(pz, 1.0f), 0.5f);

    const int l0 = 2 * k;
    const int l1 = 2 * k + 1;

    const float r0 = rp.resm1[l0];
    const float r1 = rp.resm1[l1];

    // scaled = x_norm * (res - 1); truncating cast == floor (operands >= 0)
    const uint32_t gx0 = (uint32_t)__fmul_rn(xn, r0);
    const uint32_t gy0 = (uint32_t)__fmul_rn(yn, r0);
    const uint32_t gz0 = (uint32_t)__fmul_rn(zn, r0);
    const uint32_t gx1 = (uint32_t)__fmul_rn(xn, r1);
    const uint32_t gy1 = (uint32_t)__fmul_rn(yn, r1);
    const uint32_t gz1 = (uint32_t)__fmul_rn(zn, r1);

    const uint32_t h0 =
        (gx0 ^ (gy0 * 2654435761u) ^ (gz0 * 805459861u)) & TABLE_MASK;
    const uint32_t h1 =
        (gx1 ^ (gy1 * 2654435761u) ^ (gz1 * 805459861u)) & TABLE_MASK;

    const float2* a0 = &tables[(size_t)l0 * TABLE_SIZE + h0];
    const float2* a1 = &tables[(size_t)l1 * TABLE_SIZE + h1];

    // k is uniform per thread: levels 0-1 (k==0) L1-cached, rest L2-only.
    // Compiles to predicated LDGs; wavefront count unchanged.
    const float2 f0 = (k == 0) ? __ldg(a0) : __ldcg(a0);
    const float2 f1 = (k == 0) ? __ldg(a1) : __ldcg(a1);

    // Evict-first store: output is write-once, never re-read.
    __stcs(&out[(size_t)tid], make_float4(f0.x, f0.y, f1.x, f1.y));
}

extern "C" void kernel_launch(void* const* d_in, const int* in_sizes, int n_in,
                              void* d_out, int out_size)
{
    const float*  x      = (const float*)d_in[0];
    const float2* tables = (const float2*)d_in[1];
    float4*       out    = (float4*)d_out;

    const int n = in_sizes[0] / 3;  // x has N*3 elements

    // Resolutions via the same double-precision libm chain as the Python
    // reference: b = exp((log(2048) - log(16)) / 15); res_l = int(16 * b**l).
    // Proven bit-identical (rel_err == 0.0) across all passing rounds.
    ResParams rp;
    {
        const double b = exp((log(2048.0) - log(16.0)) / 15.0);
        for (int l = 0; l < N_LEVELS; l++) {
            int res = (int)(16.0 * pow(b, (double)l));
            rp.resm1[l] = (float)res - 1.0f;
        }
    }

    const long long total = (long long)n * 8;            // one thread per float4
    const int blocks = (int)((total + THREADS - 1) / THREADS);
    hashgrid_kernel<<<blocks, THREADS>>>(x, tables, out, n, rp);
}